// round 7
// baseline (speedup 1.0000x reference)
#include <cuda_runtime.h>
#include <cstdint>
#include <cstddef>

// Problem constants
constexpr int B = 32;
constexpr int P = 196;
constexpr int D = 512;
constexpr int H = 8;
constexpr int U = 4;
constexpr int C = 500;

constexpr size_t KNOWN_ELEMS = (size_t)B * C * (H + 3) * D;  // 90,112,000
constexpr size_t UNK_ELEMS   = (size_t)B * (U + 3) * D;      // 114,688
// semantic_tokens tail: B*H*D = 131,072

// Scratch (allocation-free rule: __device__ globals)
__device__ float g_semtok[B * H * D];
__device__ float g_pdom[B * D];
__device__ float g_psem[B * H * D];

// ---------------------------------------------------------------------------
// Kernel 1: attention-pooled semantic tokens.
// One block per batch b, 512 threads. Patch tile read once coalesced for the
// accumulation phase (d = tid); scores/softmax staged in smem.
// ---------------------------------------------------------------------------
__global__ __launch_bounds__(512) void k_semtok(
    const float* __restrict__ patch,   // (B,P,D)
    const float* __restrict__ query,   // (H,D)
    float* __restrict__ out_semtok)    // (B,H,D) tail section of d_out
{
    __shared__ float s_q[H * D];      // 16 KB
    __shared__ float s_sc[P * H];     // ~6.2 KB, layout [p][h]

    const int b = blockIdx.x;
    const int tid = threadIdx.x;
    const float* pb = patch + (size_t)b * P * D;

    for (int i = tid; i < H * D; i += 512) s_q[i] = query[i];
    __syncthreads();

    // scores[p][h] = dot(patch[b,p,:], query[h,:])
    // consecutive 8 threads share a patch row (L1 broadcast); queries in smem
    for (int pair = tid; pair < P * H; pair += 512) {
        const int p = pair >> 3;
        const int h = pair & 7;
        const float4* pr = (const float4*)(pb + (size_t)p * D);
        const float4* qr = (const float4*)(s_q + h * D);
        float acc = 0.f;
        #pragma unroll 8
        for (int i = 0; i < D / 4; i++) {
            float4 a = pr[i], q = qr[i];
            acc += a.x * q.x + a.y * q.y + a.z * q.z + a.w * q.w;
        }
        s_sc[pair] = acc;
    }
    __syncthreads();

    // softmax over p (axis=1) per head; warp w handles head w
    const int w = tid >> 5, lane = tid & 31;
    if (w < H) {
        float m = -1e30f;
        for (int p = lane; p < P; p += 32) m = fmaxf(m, s_sc[p * H + w]);
        #pragma unroll
        for (int o = 16; o; o >>= 1) m = fmaxf(m, __shfl_xor_sync(0xffffffffu, m, o));
        float s = 0.f;
        for (int p = lane; p < P; p += 32) s += __expf(s_sc[p * H + w] - m);
        #pragma unroll
        for (int o = 16; o; o >>= 1) s += __shfl_xor_sync(0xffffffffu, s, o);
        const float inv = 1.0f / s;
        for (int p = lane; p < P; p += 32)
            s_sc[p * H + w] = __expf(s_sc[p * H + w] - m) * inv;
    }
    __syncthreads();

    // semantic_tokens[b,h,d] = sum_p w[p,h] * patch[b,p,d]; thread owns d=tid
    float acc[H];
    #pragma unroll
    for (int h = 0; h < H; h++) acc[h] = 0.f;
    const int d = tid;
    for (int p = 0; p < P; p++) {
        const float x = pb[(size_t)p * D + d];   // L2 hit (patch < L2 capacity)
        #pragma unroll
        for (int h = 0; h < H; h++) acc[h] += s_sc[p * H + h] * x;
    }
    #pragma unroll
    for (int h = 0; h < H; h++) {
        const float v = acc[h];
        const size_t o = ((size_t)b * H + h) * D + d;
        g_semtok[o] = v;
        out_semtok[o] = v;
    }
}

// ---------------------------------------------------------------------------
// Kernel 2: projected_domain[b,e] = sum_d gf[b,d] * dom_W[e,d] + dom_b[e]
// ---------------------------------------------------------------------------
__global__ __launch_bounds__(512) void k_pdom(
    const float* __restrict__ gf,     // (B,D)
    const float* __restrict__ Wm,     // (D,D)
    const float* __restrict__ bv)     // (D,)
{
    __shared__ float s_g[D];
    const int b = blockIdx.x;
    const int e = threadIdx.x;
    s_g[e] = gf[(size_t)b * D + e];
    __syncthreads();
    const float4* wr = (const float4*)(Wm + (size_t)e * D);
    const float4* gr = (const float4*)s_g;
    float acc = 0.f;
    #pragma unroll 8
    for (int i = 0; i < D / 4; i++) {
        float4 w4 = wr[i], g4 = gr[i];
        acc += w4.x * g4.x + w4.y * g4.y + w4.z * g4.z + w4.w * g4.w;
    }
    g_pdom[(size_t)b * D + e] = acc + bv[e];
}

// ---------------------------------------------------------------------------
// Kernel 3: projected_sem[b,h,e] = sum_d semtok[b,h,d] * sem_W[h,e,d] + sem_b[h,e]
// One block per (b,h); sem_W (8 MB) L2-resident across the 32 b's.
// ---------------------------------------------------------------------------
__global__ __launch_bounds__(512) void k_psem(
    const float* __restrict__ semW,   // (H,D,D)
    const float* __restrict__ semb)   // (H,D)
{
    __shared__ float s_t[D];
    const int bh = blockIdx.x;
    const int h = bh & 7;
    const int e = threadIdx.x;
    s_t[e] = g_semtok[(size_t)bh * D + e];
    __syncthreads();
    const float4* wr = (const float4*)(semW + ((size_t)h * D + e) * D);
    const float4* tr = (const float4*)s_t;
    float acc = 0.f;
    #pragma unroll 8
    for (int i = 0; i < D / 4; i++) {
        float4 w4 = wr[i], t4 = tr[i];
        acc += w4.x * t4.x + w4.y * t4.y + w4.z * t4.z + w4.w * t4.w;
    }
    g_psem[(size_t)bh * D + e] = acc + semb[(size_t)h * D + e];
}

// ---------------------------------------------------------------------------
// Kernel 4: assemble known_prompts (B*C, 11, D). THE bandwidth kernel: 360 MB
// of streaming stores. One block per (b,c) prompt, 128 threads; thread v owns
// float4 lane v of every row. Sources L2-resident; stores are .cs
// (evict-first — data is never re-read by this launch).
// ---------------------------------------------------------------------------
__global__ __launch_bounds__(128) void k_known(
    const float* __restrict__ pre,    // (C,1,D)
    const float* __restrict__ suf,    // (C,1,D)
    float* __restrict__ out)
{
    const int bc = blockIdx.x;
    const int b = bc / C;
    const int c = bc - b * C;
    const int v = threadIdx.x;  // 0..127

    const float4* s_pre = (const float4*)(pre + (size_t)c * D);
    const float4* s_dom = (const float4*)(g_pdom + (size_t)b * D);
    const float4* s_sem = (const float4*)(g_psem + (size_t)b * H * D);
    const float4* s_suf = (const float4*)(suf + (size_t)c * D);
    float4* o = (float4*)(out + (size_t)bc * (H + 3) * D);

    float4 r[H + 3];
    r[0] = __ldg(s_pre + v);
    r[1] = __ldg(s_dom + v);
    #pragma unroll
    for (int h = 0; h < H; h++) r[2 + h] = __ldg(s_sem + h * (D / 4) + v);
    r[H + 2] = __ldg(s_suf + v);

    #pragma unroll
    for (int i = 0; i < H + 3; i++) __stcs(o + i * (D / 4) + v, r[i]);
}

// ---------------------------------------------------------------------------
// Kernel 5: unknown_prompts (B, 7, D), tiny.
// ---------------------------------------------------------------------------
__global__ __launch_bounds__(128) void k_unknown(
    const float* __restrict__ upre,   // (1,D)
    const float* __restrict__ usem,   // (U,D)
    const float* __restrict__ usuf,   // (1,D)
    float* __restrict__ out)          // base of unknown section
{
    const int b = blockIdx.x;
    const int v = threadIdx.x;  // 0..127
    const float4* s_dom = (const float4*)(g_pdom + (size_t)b * D);
    float4* o = (float4*)(out + (size_t)b * (U + 3) * D);

    o[0 * (D / 4) + v] = ((const float4*)upre)[v];
    o[1 * (D / 4) + v] = s_dom[v];
    #pragma unroll
    for (int u = 0; u < U; u++)
        o[(2 + u) * (D / 4) + v] = ((const float4*)usem)[u * (D / 4) + v];
    o[(U + 2) * (D / 4) + v] = ((const float4*)usuf)[v];
}

// ---------------------------------------------------------------------------
extern "C" void kernel_launch(void* const* d_in, const int* in_sizes, int n_in,
                              void* d_out, int out_size)
{
    const float* patch  = (const float*)d_in[0];   // (B,P,D)
    const float* gfeat  = (const float*)d_in[1];   // (B,D)
    const float* query  = (const float*)d_in[2];   // (H,D)
    const float* dom_W  = (const float*)d_in[3];   // (D,D)
    const float* dom_b  = (const float*)d_in[4];   // (D,)
    const float* sem_W  = (const float*)d_in[5];   // (H,D,D)
    const float* sem_b  = (const float*)d_in[6];   // (H,D)
    const float* usem   = (const float*)d_in[7];   // (U,D)
    const float* kpre   = (const float*)d_in[8];   // (C,1,D)
    const float* ksuf   = (const float*)d_in[9];   // (C,1,D)
    const float* upre   = (const float*)d_in[10];  // (1,D)
    const float* usuf   = (const float*)d_in[11];  // (1,D)

    float* out = (float*)d_out;
    float* out_unknown = out + KNOWN_ELEMS;
    float* out_semtok  = out + KNOWN_ELEMS + UNK_ELEMS;

    k_semtok<<<B, 512>>>(patch, query, out_semtok);
    k_pdom<<<B, 512>>>(gfeat, dom_W, dom_b);
    k_psem<<<B * H, 512>>>(sem_W, sem_b);
    k_unknown<<<B, 128>>>(upre, usem, usuf, out_unknown);
    k_known<<<B * C, 128>>>(kpre, ksuf, out);
}